// round 15
// baseline (speedup 1.0000x reference)
#include <cuda_runtime.h>
#include <cuda_bf16.h>
#include <stdint.h>
#include <math.h>

#define Bn   4
#define Tn   2048
#define En   1024
#define Hn   16
#define HDn  64
#define Mn   (Bn * Tn)          // 8192
#define QKVN (3 * En)           // 3072

// ---------------- scratch (__device__ globals; no cudaMalloc allowed) -------
__device__ float g_qkv[(size_t)Mn * QKVN];            // 96 MB (tf32-rounded, q pre-scaled)
__device__ float g_ctx[(size_t)Mn * En];              // 32 MB (tf32-rounded)
__device__ float g_xr [(size_t)Mn * En];              // 32 MB x rounded
__device__ float g_wr [(size_t)QKVN * En];            // 12 MB qkv_w rounded (+q scale)
__device__ float g_pwr[(size_t)En * En];              //  4 MB proj_w rounded
__device__ float g_qb [QKVN];                         // qkv bias (q part scaled)

// ---------------- helpers ----------------------------------------------------
__device__ __forceinline__ uint32_t smem_u32(const void* p) {
    uint32_t a;
    asm("{ .reg .u64 t; cvta.to.shared.u64 t, %1; cvt.u32.u64 %0, t; }"
        : "=r"(a) : "l"(p));
    return a;
}
__device__ __forceinline__ void cp16(uint32_t saddr, const void* g) {
    asm volatile("cp.async.cg.shared.global [%0], [%1], 16;"
                 :: "r"(saddr), "l"(g));
}
template <int N>
__device__ __forceinline__ void cp_wait() {
    asm volatile("cp.async.wait_group %0;" :: "n"(N) : "memory");
}
__device__ __forceinline__ void cp_commit() {
    asm volatile("cp.async.commit_group;" ::: "memory");
}
__device__ __forceinline__ void ldsm4(uint32_t& r0, uint32_t& r1,
                                      uint32_t& r2, uint32_t& r3,
                                      uint32_t addr) {
    asm volatile("ldmatrix.sync.aligned.m8n8.x4.shared.b16 {%0,%1,%2,%3}, [%4];"
                 : "=r"(r0), "=r"(r1), "=r"(r2), "=r"(r3) : "r"(addr));
}
__device__ __forceinline__ void ldsm2(uint32_t& r0, uint32_t& r1,
                                      uint32_t addr) {
    asm volatile("ldmatrix.sync.aligned.m8n8.x2.shared.b16 {%0,%1}, [%2];"
                 : "=r"(r0), "=r"(r1) : "r"(addr));
}
__device__ __forceinline__ uint32_t sw128(uint32_t off) {
    return off ^ ((off >> 3) & 0x70);
}
// tf32 helpers
__device__ __forceinline__ uint32_t f2tf(float x) {
    uint32_t r;
    asm("cvt.rna.tf32.f32 %0, %1;" : "=r"(r) : "f"(x));
    return r;
}
__device__ __forceinline__ float f2tf_f(float x) {
    return __uint_as_float(f2tf(x));
}
__device__ __forceinline__ void mma_tf32(float* d, uint32_t a0, uint32_t a1,
                                         uint32_t a2, uint32_t a3,
                                         uint32_t b0, uint32_t b1) {
    asm volatile(
        "mma.sync.aligned.m16n8k8.row.col.f32.tf32.tf32.f32 "
        "{%0,%1,%2,%3}, {%4,%5,%6,%7}, {%8,%9}, {%0,%1,%2,%3};"
        : "+f"(d[0]), "+f"(d[1]), "+f"(d[2]), "+f"(d[3])
        : "r"(a0), "r"(a1), "r"(a2), "r"(a3), "r"(b0), "r"(b1));
}

// ---------------------------------------------------------------------------
// Elementwise tf32 pre-round with scale: out[i] = tf32(in[i] * scale)
// ---------------------------------------------------------------------------
__global__ void roundcvt(const float* __restrict__ in, float* __restrict__ out,
                         float scale) {
    size_t i = ((size_t)blockIdx.x * blockDim.x + threadIdx.x) * 4;
    float4 v = *(const float4*)(in + i);
    v.x = f2tf_f(v.x * scale); v.y = f2tf_f(v.y * scale);
    v.z = f2tf_f(v.z * scale); v.w = f2tf_f(v.w * scale);
    *(float4*)(out + i) = v;
}
// bias prep: scale q-part by 0.125 (bias added pre-round in GEMM epilogue)
__global__ void biasprep(const float* __restrict__ in, float* __restrict__ out) {
    int i = blockIdx.x * blockDim.x + threadIdx.x;   // 0..3071
    float v = in[i];
    out[i] = (i < En) ? v * 0.125f : v;
}

// ---------------------------------------------------------------------------
// tf32 GEMM with cp.async fill (round-12 structure, verified).
// round_out: 1 -> epilogue stores tf32-rounded values (feeds attention raw).
// ---------------------------------------------------------------------------
#define GEMM_SMEM (2 * 32768)

__global__ __launch_bounds__(256, 2)
void gemm_tf32ca(const float* __restrict__ A, const float* __restrict__ W,
                 const float* __restrict__ bias, float* __restrict__ C,
                 int Np, int round_out) {
    extern __shared__ char gsm[];
    uint32_t sb = smem_u32(gsm);
    const int K = 1024;

    int tid = threadIdx.x;
    int lane = tid & 31;
    int wid = tid >> 5;
    int wm = wid & 3;
    int wn = wid >> 2;
    int m0 = blockIdx.y * 128;
    int n0 = blockIdx.x * 128;

    uint32_t a_soff[4], b_soff[4];
    const char* a_g[4]; const char* b_g[4];
#pragma unroll
    for (int i = 0; i < 4; i++) {
        int c = tid + i * 256;
        int row = c >> 3, ch = c & 7;
        uint32_t off = row * 128 + ch * 16;
        a_soff[i] = sw128(off);
        b_soff[i] = sw128(off) + 16384;
        a_g[i] = (const char*)(A + (size_t)(m0 + row) * K + ch * 4);
        b_g[i] = (const char*)(W + (size_t)(n0 + row) * K + ch * 4);
    }

    int t = lane >> 3;
    uint32_t xm = (uint32_t)((lane & 7) << 4);
    uint32_t a_row = (uint32_t)((wm * 32 + (t & 1) * 8 + (lane & 7)) * 128);
    uint32_t a_csel = (uint32_t)((t >> 1) * 16);
    uint32_t b_row = 16384u + (uint32_t)((wn * 64 + (lane & 7)) * 128);
    uint32_t b_csel = (uint32_t)(((lane >> 3) & 1) * 16);

    float acc[2][8][4];
#pragma unroll
    for (int mt = 0; mt < 2; mt++)
#pragma unroll
        for (int nt = 0; nt < 8; nt++)
#pragma unroll
            for (int j = 0; j < 4; j++) acc[mt][nt][j] = 0.0f;

    const int NS = K / 32;

#pragma unroll
    for (int s = 0; s < 2; s++) {
        uint32_t base = sb + s * 32768;
        size_t goff = (size_t)s * 128;
#pragma unroll
        for (int i = 0; i < 4; i++) cp16(base + a_soff[i], a_g[i] + goff);
#pragma unroll
        for (int i = 0; i < 4; i++) cp16(base + b_soff[i], b_g[i] + goff);
        cp_commit();
    }

    for (int s = 0; s < NS; s++) {
        if (s == NS - 1) cp_wait<0>(); else cp_wait<1>();
        __syncthreads();

        int buf = s & 1;
        uint32_t base = sb + buf * 32768;
#pragma unroll
        for (int kk = 0; kk < 4; kk++) {
            uint32_t a0[4], a1[4];
            uint32_t ac = ((uint32_t)(kk * 32) + a_csel) ^ xm;
            ldsm4(a0[0], a0[1], a0[2], a0[3], base + a_row + ac);
            ldsm4(a1[0], a1[1], a1[2], a1[3], base + a_row + 2048 + ac);
            uint32_t bc = ((uint32_t)(kk * 32) + b_csel) ^ xm;
#pragma unroll
            for (int nt = 0; nt < 8; nt++) {
                uint32_t b0, b1;
                ldsm2(b0, b1, base + b_row + nt * 1024 + bc);
                mma_tf32(acc[0][nt], a0[0], a0[1], a0[2], a0[3], b0, b1);
                mma_tf32(acc[1][nt], a1[0], a1[1], a1[2], a1[3], b0, b1);
            }
        }
        __syncthreads();

        if (s + 2 < NS) {
            uint32_t nbase = sb + buf * 32768;
            size_t goff = (size_t)(s + 2) * 128;
#pragma unroll
            for (int i = 0; i < 4; i++) cp16(nbase + a_soff[i], a_g[i] + goff);
#pragma unroll
            for (int i = 0; i < 4; i++) cp16(nbase + b_soff[i], b_g[i] + goff);
            cp_commit();
        }
    }

#pragma unroll
    for (int mt = 0; mt < 2; mt++) {
#pragma unroll
        for (int nt = 0; nt < 8; nt++) {
            int row = m0 + wm * 32 + mt * 16 + (lane >> 2);
            int col = n0 + wn * 64 + nt * 8 + (lane & 3) * 2;
            float2 bv = *(const float2*)(bias + col);
            float2 v0 = make_float2(acc[mt][nt][0] + bv.x,
                                    acc[mt][nt][1] + bv.y);
            float2 v1 = make_float2(acc[mt][nt][2] + bv.x,
                                    acc[mt][nt][3] + bv.y);
            if (round_out) {
                v0.x = f2tf_f(v0.x); v0.y = f2tf_f(v0.y);
                v1.x = f2tf_f(v1.x); v1.y = f2tf_f(v1.y);
            }
            float* p0 = C + (size_t)row * Np + col;
            *(float2*)p0 = v0;
            float* p1 = p0 + 8 * (size_t)Np;
            *(float2*)p1 = v1;
        }
    }
}

// ---------------------------------------------------------------------------
// Flash attention, tf32 HMMA, register P-reuse (round-13 fill structure:
// LDG float4 -> STS float4, no cvt — qkv is pre-rounded, q pre-scaled).
// Block = 128 threads / 4 warps; warp M-tile = 32 q rows; KV tiles of 64.
// smem: Qs[128][68], Ks[64][68], Vt[64][68] (kv-permuted), Ms[64]
// ---------------------------------------------------------------------------
#define APAD 68
#define ATTN4_SMEM ((128 * APAD + 64 * APAD + 64 * APAD + 64) * 4)

__global__ __launch_bounds__(128)
void attn_tc(const float* __restrict__ qkv,
             const unsigned char* __restrict__ mask,
             float* __restrict__ ctx) {
    extern __shared__ float sm2[];
    float* Qs = sm2;                    // [128][APAD]
    float* Ks = Qs + 128 * APAD;        // [64][APAD]
    float* Vt = Ks + 64 * APAD;         // [64][APAD]  Vt[d][pk(kv)]
    float* Ms = Vt + 64 * APAD;         // [64]

    int tid = threadIdx.x;
    int lane = tid & 31;
    int w = tid >> 5;
    int b  = blockIdx.y >> 4;
    int h  = blockIdx.y & 15;
    int q0 = blockIdx.x * 128;
    int wrow = w * 32;

    const float* qb = qkv + (size_t)b * Tn * QKVN + h * HDn;
    const float* kb = qb + En;
    const float* vb = qb + 2 * En;

    // ---- Q fill: plain LDG -> STS (pre-rounded, pre-scaled) ----
#pragma unroll
    for (int it = 0; it < 16; it++) {
        int idx = tid + it * 128;
        int r = idx >> 4;
        int c4 = (idx & 15) * 4;
        float4 v = *(const float4*)(qb + (size_t)(q0 + r) * QKVN + c4);
        *(float4*)&Qs[r * APAD + c4] = v;
    }

    int r0 = lane >> 2;
    int cq = lane & 3;

    uint32_t sb = smem_u32(sm2);
    int t  = lane >> 3;
    int arow = (t & 1) * 8 + (lane & 7);
    int acol = (t >> 1) * 4;
    uint32_t qs_a = sb + (uint32_t)(((wrow + arow) * APAD + acol) * 4);
    int brow = lane & 7;
    int bsel = (lane >> 3) & 1;
    uint32_t ks_b = sb + (uint32_t)((128 * APAD) * 4)
                       + (uint32_t)((brow * APAD + bsel * 4) * 4);
    uint32_t vt_b = sb + (uint32_t)((128 * APAD + 64 * APAD) * 4)
                       + (uint32_t)((brow * APAD + bsel * 4) * 4);
    const uint32_t MT_STEP = 16 * APAD * 4;
    const uint32_t N_STEP  = 8 * APAD * 4;

    float oacc[2][8][4];
#pragma unroll
    for (int mt = 0; mt < 2; mt++)
#pragma unroll
        for (int n = 0; n < 8; n++)
#pragma unroll
            for (int j = 0; j < 4; j++) oacc[mt][n][j] = 0.0f;
    float mrow[2][2] = {{-1e30f, -1e30f}, {-1e30f, -1e30f}};
    float lrow[2][2] = {{0.0f, 0.0f}, {0.0f, 0.0f}};

    for (int kv0 = 0; kv0 < Tn; kv0 += 64) {
        // ---- K fill: LDG -> STS (pre-rounded) ----
#pragma unroll
        for (int it = 0; it < 8; it++) {
            int idx = tid + it * 128;
            int r = idx >> 4;
            int c4 = (idx & 15) * 4;
            float4 v = *(const float4*)(kb + (size_t)(kv0 + r) * QKVN + c4);
            *(float4*)&Ks[r * APAD + c4] = v;
        }
        // ---- V fill transposed + kv-permuted (raw) ----
#pragma unroll
        for (int it = 0; it < 8; it++) {
            int idx = tid + it * 128;
            int r = idx & 63;                 // kv row
            int c4 = (idx >> 6) * 4;          // d base
            float4 v = *(const float4*)(vb + (size_t)(kv0 + r) * QKVN + c4);
            int pr = (r & ~7) | ((r & 1) << 2) | ((r >> 1) & 3);
            Vt[(c4 + 0) * APAD + pr] = v.x;
            Vt[(c4 + 1) * APAD + pr] = v.y;
            Vt[(c4 + 2) * APAD + pr] = v.z;
            Vt[(c4 + 3) * APAD + pr] = v.w;
        }
        if (tid < 64)
            Ms[tid] = mask[b * Tn + kv0 + tid] ? -1e30f : 0.0f;
        __syncthreads();

        // ---- S = Q K^T ----
        float sacc[2][8][4];
#pragma unroll
        for (int mt = 0; mt < 2; mt++)
#pragma unroll
            for (int n = 0; n < 8; n++)
#pragma unroll
                for (int j = 0; j < 4; j++) sacc[mt][n][j] = 0.0f;

#pragma unroll
        for (int k = 0; k < 8; k++) {
            uint32_t a0[4], a1[4];
            ldsm4(a0[0], a0[1], a0[2], a0[3], qs_a + k * 32);
            ldsm4(a1[0], a1[1], a1[2], a1[3], qs_a + MT_STEP + k * 32);
#pragma unroll
            for (int n = 0; n < 8; n++) {
                uint32_t b0, b1;
                ldsm2(b0, b1, ks_b + n * N_STEP + k * 32);
                mma_tf32(sacc[0][n], a0[0], a0[1], a0[2], a0[3], b0, b1);
                mma_tf32(sacc[1][n], a1[0], a1[1], a1[2], a1[3], b0, b1);
            }
        }

        // ---- mask + online softmax ----
#pragma unroll
        for (int mt = 0; mt < 2; mt++) {
            float mx0 = -1e30f, mx1 = -1e30f;
#pragma unroll
            for (int n = 0; n < 8; n++) {
                int c = n * 8 + cq * 2;
                float ma = Ms[c], mb2 = Ms[c + 1];
                sacc[mt][n][0] += ma; sacc[mt][n][1] += mb2;
                sacc[mt][n][2] += ma; sacc[mt][n][3] += mb2;
                mx0 = fmaxf(mx0, fmaxf(sacc[mt][n][0], sacc[mt][n][1]));
                mx1 = fmaxf(mx1, fmaxf(sacc[mt][n][2], sacc[mt][n][3]));
            }
            mx0 = fmaxf(mx0, __shfl_xor_sync(0xffffffffu, mx0, 1));
            mx0 = fmaxf(mx0, __shfl_xor_sync(0xffffffffu, mx0, 2));
            mx1 = fmaxf(mx1, __shfl_xor_sync(0xffffffffu, mx1, 1));
            mx1 = fmaxf(mx1, __shfl_xor_sync(0xffffffffu, mx1, 2));

            float nm0 = fmaxf(mrow[mt][0], mx0);
            float nm1 = fmaxf(mrow[mt][1], mx1);
            float al0 = __expf(mrow[mt][0] - nm0);
            float al1 = __expf(mrow[mt][1] - nm1);
            float rs0 = 0.0f, rs1 = 0.0f;
#pragma unroll
            for (int n = 0; n < 8; n++) {
                sacc[mt][n][0] = __expf(sacc[mt][n][0] - nm0);
                sacc[mt][n][1] = __expf(sacc[mt][n][1] - nm0);
                sacc[mt][n][2] = __expf(sacc[mt][n][2] - nm1);
                sacc[mt][n][3] = __expf(sacc[mt][n][3] - nm1);
                rs0 += sacc[mt][n][0] + sacc[mt][n][1];
                rs1 += sacc[mt][n][2] + sacc[mt][n][3];
            }
            rs0 += __shfl_xor_sync(0xffffffffu, rs0, 1);
            rs0 += __shfl_xor_sync(0xffffffffu, rs0, 2);
            rs1 += __shfl_xor_sync(0xffffffffu, rs1, 1);
            rs1 += __shfl_xor_sync(0xffffffffu, rs1, 2);

            lrow[mt][0] = lrow[mt][0] * al0 + rs0;  mrow[mt][0] = nm0;
            lrow[mt][1] = lrow[mt][1] * al1 + rs1;  mrow[mt][1] = nm1;
#pragma unroll
            for (int n = 0; n < 8; n++) {
                oacc[mt][n][0] *= al0; oacc[mt][n][1] *= al0;
                oacc[mt][n][2] *= al1; oacc[mt][n][3] *= al1;
            }
        }

        // ---- O += P V (P from registers; V kv-permuted in smem) ----
#pragma unroll
        for (int k = 0; k < 8; k++) {
            uint32_t p00 = f2tf(sacc[0][k][0]);
            uint32_t p01 = f2tf(sacc[0][k][2]);
            uint32_t p02 = f2tf(sacc[0][k][1]);
            uint32_t p03 = f2tf(sacc[0][k][3]);
            uint32_t p10 = f2tf(sacc[1][k][0]);
            uint32_t p11 = f2tf(sacc[1][k][2]);
            uint32_t p12 = f2tf(sacc[1][k][1]);
            uint32_t p13 = f2tf(sacc[1][k][3]);
#pragma unroll
            for (int n = 0; n < 8; n++) {
                uint32_t b0, b1;
                ldsm2(b0, b1, vt_b + n * N_STEP + k * 32);
                mma_tf32(oacc[0][n], p00, p01, p02, p03, b0, b1);
                mma_tf32(oacc[1][n], p10, p11, p12, p13, b0, b1);
            }
        }
        __syncthreads();
    }

    // ---- epilogue (ctx tf32-rounded for proj raw feed) ----
#pragma unroll
    for (int mt = 0; mt < 2; mt++) {
        float inv0 = 1.0f / lrow[mt][0];
        float inv1 = 1.0f / lrow[mt][1];
        int row = q0 + wrow + mt * 16 + r0;
#pragma unroll
        for (int n = 0; n < 8; n++) {
            int col = h * HDn + n * 8 + cq * 2;
            float* p0 = &ctx[((size_t)b * Tn + row) * En + col];
            *(float2*)p0 = make_float2(f2tf_f(oacc[mt][n][0] * inv0),
                                       f2tf_f(oacc[mt][n][1] * inv0));
            float* p1 = &ctx[((size_t)b * Tn + row + 8) * En + col];
            *(float2*)p1 = make_float2(f2tf_f(oacc[mt][n][2] * inv1),
                                       f2tf_f(oacc[mt][n][3] * inv1));
        }
    }
}

// ---------------------------------------------------------------------------
extern "C" void kernel_launch(void* const* d_in, const int* in_sizes, int n_in,
                              void* d_out, int out_size) {
    const float*         x      = (const float*)d_in[0];
    const unsigned char* mask   = (const unsigned char*)d_in[1];
    const float*         qkv_w  = (const float*)d_in[2];
    const float*         qkv_b  = (const float*)d_in[3];
    const float*         proj_w = (const float*)d_in[4];
    const float*         proj_b = (const float*)d_in[5];
    float*               out    = (float*)d_out;

    float *qkv_s, *ctx_s, *xr, *wr, *pwr, *qbb;
    cudaGetSymbolAddress((void**)&qkv_s, g_qkv);
    cudaGetSymbolAddress((void**)&ctx_s, g_ctx);
    cudaGetSymbolAddress((void**)&xr,  g_xr);
    cudaGetSymbolAddress((void**)&wr,  g_wr);
    cudaGetSymbolAddress((void**)&pwr, g_pwr);
    cudaGetSymbolAddress((void**)&qbb, g_qb);

    cudaFuncSetAttribute(gemm_tf32ca,
                         cudaFuncAttributeMaxDynamicSharedMemorySize, GEMM_SMEM);
    cudaFuncSetAttribute(attn_tc,
                         cudaFuncAttributeMaxDynamicSharedMemorySize, ATTN4_SMEM);

    // 0) pre-round operands; fold softmax 1/8 into q rows of W and bias
    roundcvt<<<(size_t)Mn * En / 4 / 256, 256>>>(x, xr, 1.0f);
    roundcvt<<<(size_t)En * En / 4 / 256, 256>>>(qkv_w, wr, 0.125f);          // q rows
    roundcvt<<<(size_t)2 * En * En / 4 / 256, 256>>>(qkv_w + (size_t)En * En,
                                                     wr + (size_t)En * En, 1.0f);
    roundcvt<<<(size_t)En * En / 4 / 256, 256>>>(proj_w, pwr, 1.0f);
    biasprep<<<QKVN / 256, 256>>>(qkv_b, qbb);

    // 1) QKV GEMM (rounded output; q pre-scaled)
    {
        dim3 grid(QKVN / 128, Mn / 128);
        gemm_tf32ca<<<grid, 256, GEMM_SMEM>>>(xr, wr, qbb, qkv_s, QKVN, 1);
    }

    // 2) attention (round-13 fill structure, cvt-free)
    {
        dim3 grid(Tn / 128, Bn * Hn);
        attn_tc<<<grid, 128, ATTN4_SMEM>>>(qkv_s, mask, ctx_s);
    }

    // 3) proj GEMM (raw fp32 output)
    {
        dim3 grid(En / 128, Mn / 128);
        gemm_tf32ca<<<grid, 256, GEMM_SMEM>>>(ctx_s, pwr, proj_b, out, En, 0);
    }
}

// round 16
// speedup vs baseline: 1.0918x; 1.0918x over previous
#include <cuda_runtime.h>
#include <cuda_bf16.h>
#include <stdint.h>
#include <math.h>

#define Bn   4
#define Tn   2048
#define En   1024
#define Hn   16
#define HDn  64
#define Mn   (Bn * Tn)          // 8192
#define QKVN (3 * En)           // 3072

// ---------------- scratch (__device__ globals; no cudaMalloc allowed) -------
__device__ float g_qkv[(size_t)Mn * QKVN];            // 96 MB (tf32-rounded, q pre-scaled)
__device__ float g_ctx[(size_t)Mn * En];              // 32 MB (tf32-rounded)
__device__ float g_xr [(size_t)Mn * En];              // 32 MB x rounded
__device__ float g_wr [(size_t)QKVN * En];            // 12 MB qkv_w rounded (+q scale)
__device__ float g_pwr[(size_t)En * En];              //  4 MB proj_w rounded
__device__ float g_qb [QKVN];                         // qkv bias (q part scaled)

// ---------------- helpers ----------------------------------------------------
__device__ __forceinline__ uint32_t smem_u32(const void* p) {
    uint32_t a;
    asm("{ .reg .u64 t; cvta.to.shared.u64 t, %1; cvt.u32.u64 %0, t; }"
        : "=r"(a) : "l"(p));
    return a;
}
__device__ __forceinline__ void cp16(uint32_t saddr, const void* g) {
    asm volatile("cp.async.cg.shared.global [%0], [%1], 16;"
                 :: "r"(saddr), "l"(g));
}
template <int N>
__device__ __forceinline__ void cp_wait() {
    asm volatile("cp.async.wait_group %0;" :: "n"(N) : "memory");
}
__device__ __forceinline__ void cp_commit() {
    asm volatile("cp.async.commit_group;" ::: "memory");
}
__device__ __forceinline__ void ldsm4(uint32_t& r0, uint32_t& r1,
                                      uint32_t& r2, uint32_t& r3,
                                      uint32_t addr) {
    asm volatile("ldmatrix.sync.aligned.m8n8.x4.shared.b16 {%0,%1,%2,%3}, [%4];"
                 : "=r"(r0), "=r"(r1), "=r"(r2), "=r"(r3) : "r"(addr));
}
__device__ __forceinline__ void ldsm2(uint32_t& r0, uint32_t& r1,
                                      uint32_t addr) {
    asm volatile("ldmatrix.sync.aligned.m8n8.x2.shared.b16 {%0,%1}, [%2];"
                 : "=r"(r0), "=r"(r1) : "r"(addr));
}
__device__ __forceinline__ uint32_t sw128(uint32_t off) {
    return off ^ ((off >> 3) & 0x70);
}
// tf32 helpers
__device__ __forceinline__ uint32_t f2tf(float x) {
    uint32_t r;
    asm("cvt.rna.tf32.f32 %0, %1;" : "=r"(r) : "f"(x));
    return r;
}
__device__ __forceinline__ float f2tf_f(float x) {
    return __uint_as_float(f2tf(x));
}
__device__ __forceinline__ void mma_tf32(float* d, uint32_t a0, uint32_t a1,
                                         uint32_t a2, uint32_t a3,
                                         uint32_t b0, uint32_t b1) {
    asm volatile(
        "mma.sync.aligned.m16n8k8.row.col.f32.tf32.tf32.f32 "
        "{%0,%1,%2,%3}, {%4,%5,%6,%7}, {%8,%9}, {%0,%1,%2,%3};"
        : "+f"(d[0]), "+f"(d[1]), "+f"(d[2]), "+f"(d[3])
        : "r"(a0), "r"(a1), "r"(a2), "r"(a3), "r"(b0), "r"(b1));
}

// ---------------------------------------------------------------------------
// Elementwise tf32 pre-round with scale: out[i] = tf32(in[i] * scale)
// ---------------------------------------------------------------------------
__global__ void roundcvt(const float* __restrict__ in, float* __restrict__ out,
                         float scale) {
    size_t i = ((size_t)blockIdx.x * blockDim.x + threadIdx.x) * 4;
    float4 v = *(const float4*)(in + i);
    v.x = f2tf_f(v.x * scale); v.y = f2tf_f(v.y * scale);
    v.z = f2tf_f(v.z * scale); v.w = f2tf_f(v.w * scale);
    *(float4*)(out + i) = v;
}
// bias prep: scale q-part by 0.125
__global__ void biasprep(const float* __restrict__ in, float* __restrict__ out) {
    int i = blockIdx.x * blockDim.x + threadIdx.x;   // 0..3071
    float v = in[i];
    out[i] = (i < En) ? v * 0.125f : v;
}

// ---------------------------------------------------------------------------
// tf32 GEMM with cp.async fill (verified round-12/14 structure).
// round_out: 1 -> epilogue stores tf32-rounded values.
// ---------------------------------------------------------------------------
#define GEMM_SMEM (2 * 32768)

__global__ __launch_bounds__(256, 2)
void gemm_tf32ca(const float* __restrict__ A, const float* __restrict__ W,
                 const float* __restrict__ bias, float* __restrict__ C,
                 int Np, int round_out) {
    extern __shared__ char gsm[];
    uint32_t sb = smem_u32(gsm);
    const int K = 1024;

    int tid = threadIdx.x;
    int lane = tid & 31;
    int wid = tid >> 5;
    int wm = wid & 3;
    int wn = wid >> 2;
    int m0 = blockIdx.y * 128;
    int n0 = blockIdx.x * 128;

    uint32_t a_soff[4], b_soff[4];
    const char* a_g[4]; const char* b_g[4];
#pragma unroll
    for (int i = 0; i < 4; i++) {
        int c = tid + i * 256;
        int row = c >> 3, ch = c & 7;
        uint32_t off = row * 128 + ch * 16;
        a_soff[i] = sw128(off);
        b_soff[i] = sw128(off) + 16384;
        a_g[i] = (const char*)(A + (size_t)(m0 + row) * K + ch * 4);
        b_g[i] = (const char*)(W + (size_t)(n0 + row) * K + ch * 4);
    }

    int t = lane >> 3;
    uint32_t xm = (uint32_t)((lane & 7) << 4);
    uint32_t a_row = (uint32_t)((wm * 32 + (t & 1) * 8 + (lane & 7)) * 128);
    uint32_t a_csel = (uint32_t)((t >> 1) * 16);
    uint32_t b_row = 16384u + (uint32_t)((wn * 64 + (lane & 7)) * 128);
    uint32_t b_csel = (uint32_t)(((lane >> 3) & 1) * 16);

    float acc[2][8][4];
#pragma unroll
    for (int mt = 0; mt < 2; mt++)
#pragma unroll
        for (int nt = 0; nt < 8; nt++)
#pragma unroll
            for (int j = 0; j < 4; j++) acc[mt][nt][j] = 0.0f;

    const int NS = K / 32;

#pragma unroll
    for (int s = 0; s < 2; s++) {
        uint32_t base = sb + s * 32768;
        size_t goff = (size_t)s * 128;
#pragma unroll
        for (int i = 0; i < 4; i++) cp16(base + a_soff[i], a_g[i] + goff);
#pragma unroll
        for (int i = 0; i < 4; i++) cp16(base + b_soff[i], b_g[i] + goff);
        cp_commit();
    }

    for (int s = 0; s < NS; s++) {
        if (s == NS - 1) cp_wait<0>(); else cp_wait<1>();
        __syncthreads();

        int buf = s & 1;
        uint32_t base = sb + buf * 32768;
#pragma unroll
        for (int kk = 0; kk < 4; kk++) {
            uint32_t a0[4], a1[4];
            uint32_t ac = ((uint32_t)(kk * 32) + a_csel) ^ xm;
            ldsm4(a0[0], a0[1], a0[2], a0[3], base + a_row + ac);
            ldsm4(a1[0], a1[1], a1[2], a1[3], base + a_row + 2048 + ac);
            uint32_t bc = ((uint32_t)(kk * 32) + b_csel) ^ xm;
#pragma unroll
            for (int nt = 0; nt < 8; nt++) {
                uint32_t b0, b1;
                ldsm2(b0, b1, base + b_row + nt * 1024 + bc);
                mma_tf32(acc[0][nt], a0[0], a0[1], a0[2], a0[3], b0, b1);
                mma_tf32(acc[1][nt], a1[0], a1[1], a1[2], a1[3], b0, b1);
            }
        }
        __syncthreads();

        if (s + 2 < NS) {
            uint32_t nbase = sb + buf * 32768;
            size_t goff = (size_t)(s + 2) * 128;
#pragma unroll
            for (int i = 0; i < 4; i++) cp16(nbase + a_soff[i], a_g[i] + goff);
#pragma unroll
            for (int i = 0; i < 4; i++) cp16(nbase + b_soff[i], b_g[i] + goff);
            cp_commit();
        }
    }

#pragma unroll
    for (int mt = 0; mt < 2; mt++) {
#pragma unroll
        for (int nt = 0; nt < 8; nt++) {
            int row = m0 + wm * 32 + mt * 16 + (lane >> 2);
            int col = n0 + wn * 64 + nt * 8 + (lane & 3) * 2;
            float2 bv = *(const float2*)(bias + col);
            float2 v0 = make_float2(acc[mt][nt][0] + bv.x,
                                    acc[mt][nt][1] + bv.y);
            float2 v1 = make_float2(acc[mt][nt][2] + bv.x,
                                    acc[mt][nt][3] + bv.y);
            if (round_out) {
                v0.x = f2tf_f(v0.x); v0.y = f2tf_f(v0.y);
                v1.x = f2tf_f(v1.x); v1.y = f2tf_f(v1.y);
            }
            float* p0 = C + (size_t)row * Np + col;
            *(float2*)p0 = v0;
            float* p1 = p0 + 8 * (size_t)Np;
            *(float2*)p1 = v1;
        }
    }
}

// ---------------------------------------------------------------------------
// Flash attention, tf32 HMMA, register P-reuse, DOUBLE-BUFFERED KV pipeline:
// at tile i, cp.async K(i+1) and LDG V(i+1)->regs before compute; STS V and
// mask after compute; one cp_wait + one __syncthreads per tile.
// qkv pre-rounded tf32, q pre-scaled by 1/8 -> raw copies are exact.
// smem: Qs[128][68], Ks[2][64][68], Vt[2][64][68], Ms[2][64]  (~102.5 KB)
// ---------------------------------------------------------------------------
#define APAD 68
#define Q_FLOATS   (128 * APAD)            // 8704
#define KV_FLOATS  (64 * APAD)             // 4352
#define KS_OFF     Q_FLOATS                // 8704
#define VT_OFF     (Q_FLOATS + 2 * KV_FLOATS)   // 17408
#define MS_OFF     (Q_FLOATS + 4 * KV_FLOATS)   // 26112
#define ATTN5_SMEM ((MS_OFF + 128) * 4)    // 104960 B

__global__ __launch_bounds__(128)
void attn_tc(const float* __restrict__ qkv,
             const unsigned char* __restrict__ mask,
             float* __restrict__ ctx) {
    extern __shared__ float sm2[];
    float* Qs = sm2;

    int tid = threadIdx.x;
    int lane = tid & 31;
    int w = tid >> 5;
    int b  = blockIdx.y >> 4;
    int h  = blockIdx.y & 15;
    int q0 = blockIdx.x * 128;
    int wrow = w * 32;

    const float* qb = qkv + (size_t)b * Tn * QKVN + h * HDn;
    const float* kb = qb + En;
    const float* vb = qb + 2 * En;
    const unsigned char* mb = mask + b * Tn;

    uint32_t sb = smem_u32(sm2);

    // fill-slot indices (constant)
    int fr = 0, fch = 0, vr = 0, vc4 = 0, vpr = 0;
    {
        int idx = tid;                  // K fill uses idx=tid+it*128
        fr = idx >> 4; fch = idx & 15;  // pattern per-it below
        vr = idx & 63; vc4 = (idx >> 6) * 4;
        vpr = (vr & ~7) | ((vr & 1) << 2) | ((vr >> 1) & 3);
    }

    // ---- Q fill: plain LDG -> STS (pre-rounded, pre-scaled) ----
#pragma unroll
    for (int it = 0; it < 16; it++) {
        int idx = tid + it * 128;
        int r = idx >> 4;
        int c4 = (idx & 15) * 4;
        float4 v = *(const float4*)(qb + (size_t)(q0 + r) * QKVN + c4);
        *(float4*)&Qs[r * APAD + c4] = v;
    }

    int r0 = lane >> 2;
    int cq = lane & 3;

    int t  = lane >> 3;
    int arow = (t & 1) * 8 + (lane & 7);
    int acol = (t >> 1) * 4;
    uint32_t qs_a = sb + (uint32_t)(((wrow + arow) * APAD + acol) * 4);
    int brow = lane & 7;
    int bsel = (lane >> 3) & 1;
    uint32_t ks_b0 = sb + (uint32_t)(KS_OFF * 4)
                        + (uint32_t)((brow * APAD + bsel * 4) * 4);
    uint32_t vt_b0 = sb + (uint32_t)(VT_OFF * 4)
                        + (uint32_t)((brow * APAD + bsel * 4) * 4);
    const uint32_t BUFB = KV_FLOATS * 4;       // 17408 bytes per buffer
    const uint32_t MT_STEP = 16 * APAD * 4;
    const uint32_t N_STEP  = 8 * APAD * 4;

    float oacc[2][8][4];
#pragma unroll
    for (int mt = 0; mt < 2; mt++)
#pragma unroll
        for (int n = 0; n < 8; n++)
#pragma unroll
            for (int j = 0; j < 4; j++) oacc[mt][n][j] = 0.0f;
    float mrow[2][2] = {{-1e30f, -1e30f}, {-1e30f, -1e30f}};
    float lrow[2][2] = {{0.0f, 0.0f}, {0.0f, 0.0f}};

    const int NT = Tn / 64;   // 32 tiles

    // ---- prologue: tile 0 into buffer 0 ----
    {
        uint32_t kdst = sb + (uint32_t)(KS_OFF * 4);
#pragma unroll
        for (int it = 0; it < 8; it++) {
            int idx = tid + it * 128;
            int r = idx >> 4;
            int ch = idx & 15;
            cp16(kdst + (uint32_t)((r * APAD + ch * 4) * 4),
                 kb + (size_t)r * QKVN + ch * 4);
        }
        cp_commit();
        float* Vt0 = sm2 + VT_OFF;
#pragma unroll
        for (int it = 0; it < 8; it++) {
            int idx = tid + it * 128;
            int r = idx & 63;
            int c4 = (idx >> 6) * 4;
            float4 v = *(const float4*)(vb + (size_t)r * QKVN + c4);
            int pr = (r & ~7) | ((r & 1) << 2) | ((r >> 1) & 3);
            Vt0[(c4 + 0) * APAD + pr] = v.x;
            Vt0[(c4 + 1) * APAD + pr] = v.y;
            Vt0[(c4 + 2) * APAD + pr] = v.z;
            Vt0[(c4 + 3) * APAD + pr] = v.w;
        }
        if (tid < 64)
            sm2[MS_OFF + tid] = mb[tid] ? -1e30f : 0.0f;
        cp_wait<0>();
        __syncthreads();
    }

    for (int i = 0; i < NT; i++) {
        int p = i & 1;
        int kv_next = (i + 1) * 64;
        bool more = (i + 1 < NT);

        // ---- prefetch tile i+1: K via cp.async, V into regs, mask reg ----
        float4 vreg[8];
        unsigned char mreg = 0;
        if (more) {
            uint32_t kdst = sb + (uint32_t)(KS_OFF * 4) + (uint32_t)(p ^ 1) * BUFB;
#pragma unroll
            for (int it = 0; it < 8; it++) {
                int idx = tid + it * 128;
                int r = idx >> 4;
                int ch = idx & 15;
                cp16(kdst + (uint32_t)((r * APAD + ch * 4) * 4),
                     kb + (size_t)(kv_next + r) * QKVN + ch * 4);
            }
            cp_commit();
#pragma unroll
            for (int it = 0; it < 8; it++) {
                int idx = tid + it * 128;
                int r = idx & 63;
                int c4 = (idx >> 6) * 4;
                vreg[it] = *(const float4*)(vb + (size_t)(kv_next + r) * QKVN + c4);
            }
            if (tid < 64) mreg = mb[kv_next + tid];
        }

        uint32_t ks_b = ks_b0 + (uint32_t)p * BUFB;
        uint32_t vt_b = vt_b0 + (uint32_t)p * BUFB;
        const float* Msp = sm2 + MS_OFF + p * 64;

        // ---- S = Q K^T ----
        float sacc[2][8][4];
#pragma unroll
        for (int mt = 0; mt < 2; mt++)
#pragma unroll
            for (int n = 0; n < 8; n++)
#pragma unroll
                for (int j = 0; j < 4; j++) sacc[mt][n][j] = 0.0f;

#pragma unroll
        for (int k = 0; k < 8; k++) {
            uint32_t a0[4], a1[4];
            ldsm4(a0[0], a0[1], a0[2], a0[3], qs_a + k * 32);
            ldsm4(a1[0], a1[1], a1[2], a1[3], qs_a + MT_STEP + k * 32);
#pragma unroll
            for (int n = 0; n < 8; n++) {
                uint32_t b0, b1;
                ldsm2(b0, b1, ks_b + n * N_STEP + k * 32);
                mma_tf32(sacc[0][n], a0[0], a0[1], a0[2], a0[3], b0, b1);
                mma_tf32(sacc[1][n], a1[0], a1[1], a1[2], a1[3], b0, b1);
            }
        }

        // ---- mask + online softmax ----
#pragma unroll
        for (int mt = 0; mt < 2; mt++) {
            float mx0 = -1e30f, mx1 = -1e30f;
#pragma unroll
            for (int n = 0; n < 8; n++) {
                int c = n * 8 + cq * 2;
                float ma = Msp[c], mb2 = Msp[c + 1];
                sacc[mt][n][0] += ma; sacc[mt][n][1] += mb2;
                sacc[mt][n][2] += ma; sacc[mt][n][3] += mb2;
                mx0 = fmaxf(mx0, fmaxf(sacc[mt][n][0], sacc[mt][n][1]));
                mx1 = fmaxf(mx1, fmaxf(sacc[mt][n][2], sacc[mt][n][3]));
            }
            mx0 = fmaxf(mx0, __shfl_xor_sync(0xffffffffu, mx0, 1));
            mx0 = fmaxf(mx0, __shfl_xor_sync(0xffffffffu, mx0, 2));
            mx1 = fmaxf(mx1, __shfl_xor_sync(0xffffffffu, mx1, 1));
            mx1 = fmaxf(mx1, __shfl_xor_sync(0xffffffffu, mx1, 2));

            float nm0 = fmaxf(mrow[mt][0], mx0);
            float nm1 = fmaxf(mrow[mt][1], mx1);
            float al0 = __expf(mrow[mt][0] - nm0);
            float al1 = __expf(mrow[mt][1] - nm1);
            float rs0 = 0.0f, rs1 = 0.0f;
#pragma unroll
            for (int n = 0; n < 8; n++) {
                sacc[mt][n][0] = __expf(sacc[mt][n][0] - nm0);
                sacc[mt][n][1] = __expf(sacc[mt][n][1] - nm0);
                sacc[mt][n][2] = __expf(sacc[mt][n][2] - nm1);
                sacc[mt][n][3] = __expf(sacc[mt][n][3] - nm1);
                rs0 += sacc[mt][n][0] + sacc[mt][n][1];
                rs1 += sacc[mt][n][2] + sacc[mt][n][3];
            }
            rs0 += __shfl_xor_sync(0xffffffffu, rs0, 1);
            rs0 += __shfl_xor_sync(0xffffffffu, rs0, 2);
            rs1 += __shfl_xor_sync(0xffffffffu, rs1, 1);
            rs1 += __shfl_xor_sync(0xffffffffu, rs1, 2);

            lrow[mt][0] = lrow[mt][0] * al0 + rs0;  mrow[mt][0] = nm0;
            lrow[mt][1] = lrow[mt][1] * al1 + rs1;  mrow[mt][1] = nm1;
#pragma unroll
            for (int n = 0; n < 8; n++) {
                oacc[mt][n][0] *= al0; oacc[mt][n][1] *= al0;
                oacc[mt][n][2] *= al1; oacc[mt][n][3] *= al1;
            }
        }

        // ---- O += P V (P from registers; V kv-permuted in smem) ----
#pragma unroll
        for (int k = 0; k < 8; k++) {
            uint32_t p00 = f2tf(sacc[0][k][0]);
            uint32_t p01 = f2tf(sacc[0][k][2]);
            uint32_t p02 = f2tf(sacc[0][k][1]);
            uint32_t p03 = f2tf(sacc[0][k][3]);
            uint32_t p10 = f2tf(sacc[1][k][0]);
            uint32_t p11 = f2tf(sacc[1][k][2]);
            uint32_t p12 = f2tf(sacc[1][k][1]);
            uint32_t p13 = f2tf(sacc[1][k][3]);
#pragma unroll
            for (int n = 0; n < 8; n++) {
                uint32_t b0, b1;
                ldsm2(b0, b1, vt_b + n * N_STEP + k * 32);
                mma_tf32(oacc[0][n], p00, p01, p02, p03, b0, b1);
                mma_tf32(oacc[1][n], p10, p11, p12, p13, b0, b1);
            }
        }

        // ---- drain prefetch into buffer p^1 ----
        if (more) {
            float* Vtn = sm2 + VT_OFF + (p ^ 1) * KV_FLOATS;
#pragma unroll
            for (int it = 0; it < 8; it++) {
                int idx = tid + it * 128;
                int r = idx & 63;
                int c4 = (idx >> 6) * 4;
                int pr = (r & ~7) | ((r & 1) << 2) | ((r >> 1) & 3);
                Vtn[(c4 + 0) * APAD + pr] = vreg[it].x;
                Vtn[(c4 + 1) * APAD + pr] = vreg[it].y;
                Vtn[(c4 + 2) * APAD + pr] = vreg[it].z;
                Vtn[(c4 + 3) * APAD + pr] = vreg[it].w;
            }
            if (tid < 64)
                sm2[MS_OFF + (p ^ 1) * 64 + tid] = mreg ? -1e30f : 0.0f;
            cp_wait<0>();
        }
        __syncthreads();
    }

    // ---- epilogue (ctx tf32-rounded for proj raw feed) ----
#pragma unroll
    for (int mt = 0; mt < 2; mt++) {
        float inv0 = 1.0f / lrow[mt][0];
        float inv1 = 1.0f / lrow[mt][1];
        int row = q0 + wrow + mt * 16 + r0;
#pragma unroll
        for (int n = 0; n < 8; n++) {
            int col = h * HDn + n * 8 + cq * 2;
            float* p0 = &ctx[((size_t)b * Tn + row) * En + col];
            *(float2*)p0 = make_float2(f2tf_f(oacc[mt][n][0] * inv0),
                                       f2tf_f(oacc[mt][n][1] * inv0));
            float* p1 = &ctx[((size_t)b * Tn + row + 8) * En + col];
            *(float2*)p1 = make_float2(f2tf_f(oacc[mt][n][2] * inv1),
                                       f2tf_f(oacc[mt][n][3] * inv1));
        }
    }
}

// ---------------------------------------------------------------------------
extern "C" void kernel_launch(void* const* d_in, const int* in_sizes, int n_in,
                              void* d_out, int out_size) {
    const float*         x      = (const float*)d_in[0];
    const unsigned char* mask   = (const unsigned char*)d_in[1];
    const float*         qkv_w  = (const float*)d_in[2];
    const float*         qkv_b  = (const float*)d_in[3];
    const float*         proj_w = (const float*)d_in[4];
    const float*         proj_b = (const float*)d_in[5];
    float*               out    = (float*)d_out;

    float *qkv_s, *ctx_s, *xr, *wr, *pwr, *qbb;
    cudaGetSymbolAddress((void**)&qkv_s, g_qkv);
    cudaGetSymbolAddress((void**)&ctx_s, g_ctx);
    cudaGetSymbolAddress((void**)&xr,  g_xr);
    cudaGetSymbolAddress((void**)&wr,  g_wr);
    cudaGetSymbolAddress((void**)&pwr, g_pwr);
    cudaGetSymbolAddress((void**)&qbb, g_qb);

    cudaFuncSetAttribute(gemm_tf32ca,
                         cudaFuncAttributeMaxDynamicSharedMemorySize, GEMM_SMEM);
    cudaFuncSetAttribute(attn_tc,
                         cudaFuncAttributeMaxDynamicSharedMemorySize, ATTN5_SMEM);

    // 0) pre-round operands; fold softmax 1/8 into q rows of W and bias
    roundcvt<<<(size_t)Mn * En / 4 / 256, 256>>>(x, xr, 1.0f);
    roundcvt<<<(size_t)En * En / 4 / 256, 256>>>(qkv_w, wr, 0.125f);
    roundcvt<<<(size_t)2 * En * En / 4 / 256, 256>>>(qkv_w + (size_t)En * En,
                                                     wr + (size_t)En * En, 1.0f);
    roundcvt<<<(size_t)En * En / 4 / 256, 256>>>(proj_w, pwr, 1.0f);
    biasprep<<<QKVN / 256, 256>>>(qkv_b, qbb);

    // 1) QKV GEMM (rounded output; q pre-scaled)
    {
        dim3 grid(QKVN / 128, Mn / 128);
        gemm_tf32ca<<<grid, 256, GEMM_SMEM>>>(xr, wr, qbb, qkv_s, QKVN, 1);
    }

    // 2) attention (double-buffered KV pipeline)
    {
        dim3 grid(Tn / 128, Bn * Hn);
        attn_tc<<<grid, 128, ATTN5_SMEM>>>(qkv_s, mask, ctx_s);
    }

    // 3) proj GEMM (raw fp32 output)
    {
        dim3 grid(En / 128, Mn / 128);
        gemm_tf32ca<<<grid, 256, GEMM_SMEM>>>(ctx_s, pwr, proj_b, out, En, 0);
    }
}

// round 17
// speedup vs baseline: 1.0951x; 1.0031x over previous
#include <cuda_runtime.h>
#include <cuda_bf16.h>
#include <stdint.h>
#include <math.h>

#define Bn   4
#define Tn   2048
#define En   1024
#define Hn   16
#define HDn  64
#define Mn   (Bn * Tn)          // 8192
#define QKVN (3 * En)           // 3072

// ---------------- scratch (__device__ globals; no cudaMalloc allowed) -------
__device__ float g_qkv[(size_t)Mn * QKVN];            // 96 MB (tf32-rounded, q pre-scaled)
__device__ float g_ctx[(size_t)Mn * En];              // 32 MB (tf32-rounded)
__device__ float g_xr [(size_t)Mn * En];              // 32 MB x rounded
__device__ float g_wr [(size_t)QKVN * En];            // 12 MB qkv_w rounded (+q scale)
__device__ float g_pwr[(size_t)En * En];              //  4 MB proj_w rounded
__device__ float g_qb [QKVN];                         // qkv bias (q part scaled)

// Q pre-scale: (1/sqrt(64)) * log2(e)  -> softmax runs in exp2 domain
#define QSCALE (0.125f * 1.4426950408889634f)

// ---------------- helpers ----------------------------------------------------
__device__ __forceinline__ uint32_t smem_u32(const void* p) {
    uint32_t a;
    asm("{ .reg .u64 t; cvta.to.shared.u64 t, %1; cvt.u32.u64 %0, t; }"
        : "=r"(a) : "l"(p));
    return a;
}
__device__ __forceinline__ void cp16(uint32_t saddr, const void* g) {
    asm volatile("cp.async.cg.shared.global [%0], [%1], 16;"
                 :: "r"(saddr), "l"(g));
}
template <int N>
__device__ __forceinline__ void cp_wait() {
    asm volatile("cp.async.wait_group %0;" :: "n"(N) : "memory");
}
__device__ __forceinline__ void cp_commit() {
    asm volatile("cp.async.commit_group;" ::: "memory");
}
__device__ __forceinline__ void ldsm4(uint32_t& r0, uint32_t& r1,
                                      uint32_t& r2, uint32_t& r3,
                                      uint32_t addr) {
    asm volatile("ldmatrix.sync.aligned.m8n8.x4.shared.b16 {%0,%1,%2,%3}, [%4];"
                 : "=r"(r0), "=r"(r1), "=r"(r2), "=r"(r3) : "r"(addr));
}
__device__ __forceinline__ void ldsm2(uint32_t& r0, uint32_t& r1,
                                      uint32_t addr) {
    asm volatile("ldmatrix.sync.aligned.m8n8.x2.shared.b16 {%0,%1}, [%2];"
                 : "=r"(r0), "=r"(r1) : "r"(addr));
}
__device__ __forceinline__ uint32_t sw128(uint32_t off) {
    return off ^ ((off >> 3) & 0x70);
}
// tf32 helpers
__device__ __forceinline__ uint32_t f2tf(float x) {
    uint32_t r;
    asm("cvt.rna.tf32.f32 %0, %1;" : "=r"(r) : "f"(x));
    return r;
}
__device__ __forceinline__ float f2tf_f(float x) {
    return __uint_as_float(f2tf(x));
}
__device__ __forceinline__ float ex2f(float x) {
    float r;
    asm("ex2.approx.f32 %0, %1;" : "=f"(r) : "f"(x));
    return r;
}
__device__ __forceinline__ void mma_tf32(float* d, uint32_t a0, uint32_t a1,
                                         uint32_t a2, uint32_t a3,
                                         uint32_t b0, uint32_t b1) {
    asm volatile(
        "mma.sync.aligned.m16n8k8.row.col.f32.tf32.tf32.f32 "
        "{%0,%1,%2,%3}, {%4,%5,%6,%7}, {%8,%9}, {%0,%1,%2,%3};"
        : "+f"(d[0]), "+f"(d[1]), "+f"(d[2]), "+f"(d[3])
        : "r"(a0), "r"(a1), "r"(a2), "r"(a3), "r"(b0), "r"(b1));
}

// ---------------------------------------------------------------------------
// Elementwise tf32 pre-round with scale: out[i] = tf32(in[i] * scale)
// ---------------------------------------------------------------------------
__global__ void roundcvt(const float* __restrict__ in, float* __restrict__ out,
                         float scale) {
    size_t i = ((size_t)blockIdx.x * blockDim.x + threadIdx.x) * 4;
    float4 v = *(const float4*)(in + i);
    v.x = f2tf_f(v.x * scale); v.y = f2tf_f(v.y * scale);
    v.z = f2tf_f(v.z * scale); v.w = f2tf_f(v.w * scale);
    *(float4*)(out + i) = v;
}
// bias prep: scale q-part by QSCALE
__global__ void biasprep(const float* __restrict__ in, float* __restrict__ out) {
    int i = blockIdx.x * blockDim.x + threadIdx.x;   // 0..3071
    float v = in[i];
    out[i] = (i < En) ? v * QSCALE : v;
}

// ---------------------------------------------------------------------------
// tf32 GEMM, cp.async fill, 3-buffer SINGLE-SYNC pipeline.
// iter s: wait<1>; sync; issue cp(s+2)->buf[(s+2)%3]; compute buf[s%3].
// round_out: 1 -> epilogue stores tf32-rounded values.
// ---------------------------------------------------------------------------
#define GEMM_SMEM (3 * 32768)

__global__ __launch_bounds__(256, 2)
void gemm_tf32ca(const float* __restrict__ A, const float* __restrict__ W,
                 const float* __restrict__ bias, float* __restrict__ C,
                 int Np, int round_out) {
    extern __shared__ char gsm[];
    uint32_t sb = smem_u32(gsm);
    const int K = 1024;

    int tid = threadIdx.x;
    int lane = tid & 31;
    int wid = tid >> 5;
    int wm = wid & 3;
    int wn = wid >> 2;
    int m0 = blockIdx.y * 128;
    int n0 = blockIdx.x * 128;

    uint32_t a_soff[4], b_soff[4];
    const char* a_g[4]; const char* b_g[4];
#pragma unroll
    for (int i = 0; i < 4; i++) {
        int c = tid + i * 256;
        int row = c >> 3, ch = c & 7;
        uint32_t off = row * 128 + ch * 16;
        a_soff[i] = sw128(off);
        b_soff[i] = sw128(off) + 16384;
        a_g[i] = (const char*)(A + (size_t)(m0 + row) * K + ch * 4);
        b_g[i] = (const char*)(W + (size_t)(n0 + row) * K + ch * 4);
    }

    int t = lane >> 3;
    uint32_t xm = (uint32_t)((lane & 7) << 4);
    uint32_t a_row = (uint32_t)((wm * 32 + (t & 1) * 8 + (lane & 7)) * 128);
    uint32_t a_csel = (uint32_t)((t >> 1) * 16);
    uint32_t b_row = 16384u + (uint32_t)((wn * 64 + (lane & 7)) * 128);
    uint32_t b_csel = (uint32_t)(((lane >> 3) & 1) * 16);

    float acc[2][8][4];
#pragma unroll
    for (int mt = 0; mt < 2; mt++)
#pragma unroll
        for (int nt = 0; nt < 8; nt++)
#pragma unroll
            for (int j = 0; j < 4; j++) acc[mt][nt][j] = 0.0f;

    const int NS = K / 32;    // 32

    // prologue: stages 0,1 into buffers 0,1
#pragma unroll
    for (int s = 0; s < 2; s++) {
        uint32_t base = sb + s * 32768;
        size_t goff = (size_t)s * 128;
#pragma unroll
        for (int i = 0; i < 4; i++) cp16(base + a_soff[i], a_g[i] + goff);
#pragma unroll
        for (int i = 0; i < 4; i++) cp16(base + b_soff[i], b_g[i] + goff);
        cp_commit();
    }

    int buf = 0, nxt = 2;
    for (int s = 0; s < NS; s++) {
        if (s == NS - 1) cp_wait<0>(); else cp_wait<1>();
        __syncthreads();

        if (s + 2 < NS) {
            uint32_t nbase = sb + nxt * 32768;
            size_t goff = (size_t)(s + 2) * 128;
#pragma unroll
            for (int i = 0; i < 4; i++) cp16(nbase + a_soff[i], a_g[i] + goff);
#pragma unroll
            for (int i = 0; i < 4; i++) cp16(nbase + b_soff[i], b_g[i] + goff);
            cp_commit();
            nxt = (nxt + 1 == 3) ? 0 : nxt + 1;
        }

        uint32_t base = sb + buf * 32768;
#pragma unroll
        for (int kk = 0; kk < 4; kk++) {
            uint32_t a0[4], a1[4];
            uint32_t ac = ((uint32_t)(kk * 32) + a_csel) ^ xm;
            ldsm4(a0[0], a0[1], a0[2], a0[3], base + a_row + ac);
            ldsm4(a1[0], a1[1], a1[2], a1[3], base + a_row + 2048 + ac);
            uint32_t bc = ((uint32_t)(kk * 32) + b_csel) ^ xm;
#pragma unroll
            for (int nt = 0; nt < 8; nt++) {
                uint32_t b0, b1;
                ldsm2(b0, b1, base + b_row + nt * 1024 + bc);
                mma_tf32(acc[0][nt], a0[0], a0[1], a0[2], a0[3], b0, b1);
                mma_tf32(acc[1][nt], a1[0], a1[1], a1[2], a1[3], b0, b1);
            }
        }
        buf = (buf + 1 == 3) ? 0 : buf + 1;
    }

#pragma unroll
    for (int mt = 0; mt < 2; mt++) {
#pragma unroll
        for (int nt = 0; nt < 8; nt++) {
            int row = m0 + wm * 32 + mt * 16 + (lane >> 2);
            int col = n0 + wn * 64 + nt * 8 + (lane & 3) * 2;
            float2 bv = *(const float2*)(bias + col);
            float2 v0 = make_float2(acc[mt][nt][0] + bv.x,
                                    acc[mt][nt][1] + bv.y);
            float2 v1 = make_float2(acc[mt][nt][2] + bv.x,
                                    acc[mt][nt][3] + bv.y);
            if (round_out) {
                v0.x = f2tf_f(v0.x); v0.y = f2tf_f(v0.y);
                v1.x = f2tf_f(v1.x); v1.y = f2tf_f(v1.y);
            }
            float* p0 = C + (size_t)row * Np + col;
            *(float2*)p0 = v0;
            float* p1 = p0 + 8 * (size_t)Np;
            *(float2*)p1 = v1;
        }
    }
}

// ---------------------------------------------------------------------------
// Flash attention, tf32 HMMA, register P-reuse, double-buffered KV pipeline,
// softmax in exp2 domain (log2e folded into q pre-scale).
// smem: Qs[128][68], Ks[2][64][68], Vt[2][64][68], Ms[2][64]  (~102.5 KB)
// ---------------------------------------------------------------------------
#define APAD 68
#define Q_FLOATS   (128 * APAD)
#define KV_FLOATS  (64 * APAD)
#define KS_OFF     Q_FLOATS
#define VT_OFF     (Q_FLOATS + 2 * KV_FLOATS)
#define MS_OFF     (Q_FLOATS + 4 * KV_FLOATS)
#define ATTN5_SMEM ((MS_OFF + 128) * 4)

__global__ __launch_bounds__(128)
void attn_tc(const float* __restrict__ qkv,
             const unsigned char* __restrict__ mask,
             float* __restrict__ ctx) {
    extern __shared__ float sm2[];
    float* Qs = sm2;

    int tid = threadIdx.x;
    int lane = tid & 31;
    int w = tid >> 5;
    int b  = blockIdx.y >> 4;
    int h  = blockIdx.y & 15;
    int q0 = blockIdx.x * 128;
    int wrow = w * 32;

    const float* qb = qkv + (size_t)b * Tn * QKVN + h * HDn;
    const float* kb = qb + En;
    const float* vb = qb + 2 * En;
    const unsigned char* mb = mask + b * Tn;

    uint32_t sb = smem_u32(sm2);

    // ---- Q fill: plain LDG -> STS (pre-rounded, pre-scaled by QSCALE) ----
#pragma unroll
    for (int it = 0; it < 16; it++) {
        int idx = tid + it * 128;
        int r = idx >> 4;
        int c4 = (idx & 15) * 4;
        float4 v = *(const float4*)(qb + (size_t)(q0 + r) * QKVN + c4);
        *(float4*)&Qs[r * APAD + c4] = v;
    }

    int r0 = lane >> 2;
    int cq = lane & 3;

    int t  = lane >> 3;
    int arow = (t & 1) * 8 + (lane & 7);
    int acol = (t >> 1) * 4;
    uint32_t qs_a = sb + (uint32_t)(((wrow + arow) * APAD + acol) * 4);
    int brow = lane & 7;
    int bsel = (lane >> 3) & 1;
    uint32_t ks_b0 = sb + (uint32_t)(KS_OFF * 4)
                        + (uint32_t)((brow * APAD + bsel * 4) * 4);
    uint32_t vt_b0 = sb + (uint32_t)(VT_OFF * 4)
                        + (uint32_t)((brow * APAD + bsel * 4) * 4);
    const uint32_t BUFB = KV_FLOATS * 4;
    const uint32_t MT_STEP = 16 * APAD * 4;
    const uint32_t N_STEP  = 8 * APAD * 4;

    float oacc[2][8][4];
#pragma unroll
    for (int mt = 0; mt < 2; mt++)
#pragma unroll
        for (int n = 0; n < 8; n++)
#pragma unroll
            for (int j = 0; j < 4; j++) oacc[mt][n][j] = 0.0f;
    float mrow[2][2] = {{-1e30f, -1e30f}, {-1e30f, -1e30f}};
    float lrow[2][2] = {{0.0f, 0.0f}, {0.0f, 0.0f}};

    const int NT = Tn / 64;

    // ---- prologue: tile 0 into buffer 0 ----
    {
        uint32_t kdst = sb + (uint32_t)(KS_OFF * 4);
#pragma unroll
        for (int it = 0; it < 8; it++) {
            int idx = tid + it * 128;
            int r = idx >> 4;
            int ch = idx & 15;
            cp16(kdst + (uint32_t)((r * APAD + ch * 4) * 4),
                 kb + (size_t)r * QKVN + ch * 4);
        }
        cp_commit();
        float* Vt0 = sm2 + VT_OFF;
#pragma unroll
        for (int it = 0; it < 8; it++) {
            int idx = tid + it * 128;
            int r = idx & 63;
            int c4 = (idx >> 6) * 4;
            float4 v = *(const float4*)(vb + (size_t)r * QKVN + c4);
            int pr = (r & ~7) | ((r & 1) << 2) | ((r >> 1) & 3);
            Vt0[(c4 + 0) * APAD + pr] = v.x;
            Vt0[(c4 + 1) * APAD + pr] = v.y;
            Vt0[(c4 + 2) * APAD + pr] = v.z;
            Vt0[(c4 + 3) * APAD + pr] = v.w;
        }
        if (tid < 64)
            sm2[MS_OFF + tid] = mb[tid] ? -1e30f : 0.0f;
        cp_wait<0>();
        __syncthreads();
    }

    for (int i = 0; i < NT; i++) {
        int p = i & 1;
        int kv_next = (i + 1) * 64;
        bool more = (i + 1 < NT);

        // ---- prefetch tile i+1 ----
        float4 vreg[8];
        unsigned char mreg = 0;
        if (more) {
            uint32_t kdst = sb + (uint32_t)(KS_OFF * 4) + (uint32_t)(p ^ 1) * BUFB;
#pragma unroll
            for (int it = 0; it < 8; it++) {
                int idx = tid + it * 128;
                int r = idx >> 4;
                int ch = idx & 15;
                cp16(kdst + (uint32_t)((r * APAD + ch * 4) * 4),
                     kb + (size_t)(kv_next + r) * QKVN + ch * 4);
            }
            cp_commit();
#pragma unroll
            for (int it = 0; it < 8; it++) {
                int idx = tid + it * 128;
                int r = idx & 63;
                int c4 = (idx >> 6) * 4;
                vreg[it] = *(const float4*)(vb + (size_t)(kv_next + r) * QKVN + c4);
            }
            if (tid < 64) mreg = mb[kv_next + tid];
        }

        uint32_t ks_b = ks_b0 + (uint32_t)p * BUFB;
        uint32_t vt_b = vt_b0 + (uint32_t)p * BUFB;
        const float* Msp = sm2 + MS_OFF + p * 64;

        // ---- S = Q K^T (exp2-domain logits) ----
        float sacc[2][8][4];
#pragma unroll
        for (int mt = 0; mt < 2; mt++)
#pragma unroll
            for (int n = 0; n < 8; n++)
#pragma unroll
                for (int j = 0; j < 4; j++) sacc[mt][n][j] = 0.0f;

#pragma unroll
        for (int k = 0; k < 8; k++) {
            uint32_t a0[4], a1[4];
            ldsm4(a0[0], a0[1], a0[2], a0[3], qs_a + k * 32);
            ldsm4(a1[0], a1[1], a1[2], a1[3], qs_a + MT_STEP + k * 32);
#pragma unroll
            for (int n = 0; n < 8; n++) {
                uint32_t b0, b1;
                ldsm2(b0, b1, ks_b + n * N_STEP + k * 32);
                mma_tf32(sacc[0][n], a0[0], a0[1], a0[2], a0[3], b0, b1);
                mma_tf32(sacc[1][n], a1[0], a1[1], a1[2], a1[3], b0, b1);
            }
        }

        // ---- mask + online softmax (exp2 domain) ----
#pragma unroll
        for (int mt = 0; mt < 2; mt++) {
            float mx0 = -1e30f, mx1 = -1e30f;
#pragma unroll
            for (int n = 0; n < 8; n++) {
                int c = n * 8 + cq * 2;
                float ma = Msp[c], mb2 = Msp[c + 1];
                sacc[mt][n][0] += ma; sacc[mt][n][1] += mb2;
                sacc[mt][n][2] += ma; sacc[mt][n][3] += mb2;
                mx0 = fmaxf(mx0, fmaxf(sacc[mt][n][0], sacc[mt][n][1]));
                mx1 = fmaxf(mx1, fmaxf(sacc[mt][n][2], sacc[mt][n][3]));
            }
            mx0 = fmaxf(mx0, __shfl_xor_sync(0xffffffffu, mx0, 1));
            mx0 = fmaxf(mx0, __shfl_xor_sync(0xffffffffu, mx0, 2));
            mx1 = fmaxf(mx1, __shfl_xor_sync(0xffffffffu, mx1, 1));
            mx1 = fmaxf(mx1, __shfl_xor_sync(0xffffffffu, mx1, 2));

            float nm0 = fmaxf(mrow[mt][0], mx0);
            float nm1 = fmaxf(mrow[mt][1], mx1);
            float al0 = ex2f(mrow[mt][0] - nm0);
            float al1 = ex2f(mrow[mt][1] - nm1);
            float rs0 = 0.0f, rs1 = 0.0f;
#pragma unroll
            for (int n = 0; n < 8; n++) {
                sacc[mt][n][0] = ex2f(sacc[mt][n][0] - nm0);
                sacc[mt][n][1] = ex2f(sacc[mt][n][1] - nm0);
                sacc[mt][n][2] = ex2f(sacc[mt][n][2] - nm1);
                sacc[mt][n][3] = ex2f(sacc[mt][n][3] - nm1);
                rs0 += sacc[mt][n][0] + sacc[mt][n][1];
                rs1 += sacc[mt][n][2] + sacc[mt][n][3];
            }
            rs0 += __shfl_xor_sync(0xffffffffu, rs0, 1);
            rs0 += __shfl_xor_sync(0xffffffffu, rs0, 2);
            rs1 += __shfl_xor_sync(0xffffffffu, rs1, 1);
            rs1 += __shfl_xor_sync(0xffffffffu, rs1, 2);

            lrow[mt][0] = lrow[mt][0] * al0 + rs0;  mrow[mt][0] = nm0;
            lrow[mt][1] = lrow[mt][1] * al1 + rs1;  mrow[mt][1] = nm1;
#pragma unroll
            for (int n = 0; n < 8; n++) {
                oacc[mt][n][0] *= al0; oacc[mt][n][1] *= al0;
                oacc[mt][n][2] *= al1; oacc[mt][n][3] *= al1;
            }
        }

        // ---- O += P V (P from registers; V kv-permuted in smem) ----
#pragma unroll
        for (int k = 0; k < 8; k++) {
            uint32_t p00 = f2tf(sacc[0][k][0]);
            uint32_t p01 = f2tf(sacc[0][k][2]);
            uint32_t p02 = f2tf(sacc[0][k][1]);
            uint32_t p03 = f2tf(sacc[0][k][3]);
            uint32_t p10 = f2tf(sacc[1][k][0]);
            uint32_t p11 = f2tf(sacc[1][k][2]);
            uint32_t p12 = f2tf(sacc[1][k][1]);
            uint32_t p13 = f2tf(sacc[1][k][3]);
#pragma unroll
            for (int n = 0; n < 8; n++) {
                uint32_t b0, b1;
                ldsm2(b0, b1, vt_b + n * N_STEP + k * 32);
                mma_tf32(oacc[0][n], p00, p01, p02, p03, b0, b1);
                mma_tf32(oacc[1][n], p10, p11, p12, p13, b0, b1);
            }
        }

        // ---- drain prefetch into buffer p^1 ----
        if (more) {
            float* Vtn = sm2 + VT_OFF + (p ^ 1) * KV_FLOATS;
#pragma unroll
            for (int it = 0; it < 8; it++) {
                int idx = tid + it * 128;
                int r = idx & 63;
                int c4 = (idx >> 6) * 4;
                int pr = (r & ~7) | ((r & 1) << 2) | ((r >> 1) & 3);
                Vtn[(c4 + 0) * APAD + pr] = vreg[it].x;
                Vtn[(c4 + 1) * APAD + pr] = vreg[it].y;
                Vtn[(c4 + 2) * APAD + pr] = vreg[it].z;
                Vtn[(c4 + 3) * APAD + pr] = vreg[it].w;
            }
            if (tid < 64)
                sm2[MS_OFF + (p ^ 1) * 64 + tid] = mreg ? -1e30f : 0.0f;
            cp_wait<0>();
        }
        __syncthreads();
    }

    // ---- epilogue (ctx tf32-rounded for proj raw feed) ----
#pragma unroll
    for (int mt = 0; mt < 2; mt++) {
        float inv0 = 1.0f / lrow[mt][0];
        float inv1 = 1.0f / lrow[mt][1];
        int row = q0 + wrow + mt * 16 + r0;
#pragma unroll
        for (int n = 0; n < 8; n++) {
            int col = h * HDn + n * 8 + cq * 2;
            float* p0 = &ctx[((size_t)b * Tn + row) * En + col];
            *(float2*)p0 = make_float2(f2tf_f(oacc[mt][n][0] * inv0),
                                       f2tf_f(oacc[mt][n][1] * inv0));
            float* p1 = &ctx[((size_t)b * Tn + row + 8) * En + col];
            *(float2*)p1 = make_float2(f2tf_f(oacc[mt][n][2] * inv1),
                                       f2tf_f(oacc[mt][n][3] * inv1));
        }
    }
}

// ---------------------------------------------------------------------------
extern "C" void kernel_launch(void* const* d_in, const int* in_sizes, int n_in,
                              void* d_out, int out_size) {
    const float*         x      = (const float*)d_in[0];
    const unsigned char* mask   = (const unsigned char*)d_in[1];
    const float*         qkv_w  = (const float*)d_in[2];
    const float*         qkv_b  = (const float*)d_in[3];
    const float*         proj_w = (const float*)d_in[4];
    const float*         proj_b = (const float*)d_in[5];
    float*               out    = (float*)d_out;

    float *qkv_s, *ctx_s, *xr, *wr, *pwr, *qbb;
    cudaGetSymbolAddress((void**)&qkv_s, g_qkv);
    cudaGetSymbolAddress((void**)&ctx_s, g_ctx);
    cudaGetSymbolAddress((void**)&xr,  g_xr);
    cudaGetSymbolAddress((void**)&wr,  g_wr);
    cudaGetSymbolAddress((void**)&pwr, g_pwr);
    cudaGetSymbolAddress((void**)&qbb, g_qb);

    cudaFuncSetAttribute(gemm_tf32ca,
                         cudaFuncAttributeMaxDynamicSharedMemorySize, GEMM_SMEM);
    cudaFuncSetAttribute(attn_tc,
                         cudaFuncAttributeMaxDynamicSharedMemorySize, ATTN5_SMEM);

    // 0) pre-round operands; fold QSCALE into q rows of W and bias
    roundcvt<<<(size_t)Mn * En / 4 / 256, 256>>>(x, xr, 1.0f);
    roundcvt<<<(size_t)En * En / 4 / 256, 256>>>(qkv_w, wr, QSCALE);
    roundcvt<<<(size_t)2 * En * En / 4 / 256, 256>>>(qkv_w + (size_t)En * En,
                                                     wr + (size_t)En * En, 1.0f);
    roundcvt<<<(size_t)En * En / 4 / 256, 256>>>(proj_w, pwr, 1.0f);
    biasprep<<<QKVN / 256, 256>>>(qkv_b, qbb);

    // 1) QKV GEMM (rounded output; q pre-scaled)
    {
        dim3 grid(QKVN / 128, Mn / 128);
        gemm_tf32ca<<<grid, 256, GEMM_SMEM>>>(xr, wr, qbb, qkv_s, QKVN, 1);
    }

    // 2) attention (double-buffered KV pipeline, exp2 softmax)
    {
        dim3 grid(Tn / 128, Bn * Hn);
        attn_tc<<<grid, 128, ATTN5_SMEM>>>(qkv_s, mask, ctx_s);
    }

    // 3) proj GEMM (raw fp32 output)
    {
        dim3 grid(En / 128, Mn / 128);
        gemm_tf32ca<<<grid, 256, GEMM_SMEM>>>(ctx_s, pwr, proj_b, out, En, 0);
    }
}